// round 17
// baseline (speedup 1.0000x reference)
#include <cuda_runtime.h>

// Problem constants (fixed by the dataset)
#define B_   128
#define E_   100000
#define F_   5000
#define C_   8
#define DIN_ 10
#define DOUT_ 10
#define H_   (F_ * C_)
#define EPS_ 1e-5f
#define CB_  64   // batch columns per chunk (2 chunks)

// Scratch (static device mem).
__device__ float g_xT[(size_t)E_ * B_];    // xT[e][b] (only gather-used rows written)
__device__ float g_outT[(size_t)E_ * B_];  // outT[e][b] = x + b3, scatter target
__device__ unsigned char g_used[E_];       // per-edge gather flag

// ---------------------------------------------------------------------------
// Kernel M: mark edges that appear as gather sources.
// ---------------------------------------------------------------------------
__global__ __launch_bounds__(256)
void mark_used_kernel(const int* __restrict__ src1) {
    int i = blockIdx.x * blockDim.x + threadIdx.x;
    if (i < F_ * DIN_) g_used[src1[i * C_]] = 1;
}

// ---------------------------------------------------------------------------
// Kernel A(chunk): transpose x[b0..b0+64) -> xT/outT columns [b0..b0+64).
// Tile 32e x 64b, block (8,32). xT stores predicated on g_used.
// ---------------------------------------------------------------------------
__global__ __launch_bounds__(256)
void transpose_init_chunk(const float* __restrict__ x,
                          const float* __restrict__ b3, int b0) {
    __shared__ float tile[32][65];            // tile[e_loc][b_loc]
    const int e0 = blockIdx.x * 32;
    const int tx = threadIdx.x;               // 0..7
    const int ty = threadIdx.y;               // 0..31

#pragma unroll
    for (int j = 0; j < 2; j++) {
        const int bl = ty + 32 * j;
        float4 v = __ldcs(reinterpret_cast<const float4*>(
                              x + (size_t)(b0 + bl) * E_ + e0) + tx);
        tile[tx * 4 + 0][bl] = v.x;
        tile[tx * 4 + 1][bl] = v.y;
        tile[tx * 4 + 2][bl] = v.z;
        tile[tx * 4 + 3][bl] = v.w;
    }
    __syncthreads();
    {
        const int e = e0 + ty;
        const bool used = (g_used[e] != 0);
        const float bias = __ldg(b3 + e);
        const size_t row = (size_t)e * B_ + b0;
#pragma unroll
        for (int k = 0; k < 2; k++) {
            const int bb = 4 * (tx + 8 * k);
            float4 w;
            w.x = tile[ty][bb + 0];
            w.y = tile[ty][bb + 1];
            w.z = tile[ty][bb + 2];
            w.w = tile[ty][bb + 3];
            if (used) *reinterpret_cast<float4*>(&g_xT[row + bb]) = w;
            float4 w2;
            w2.x = w.x + bias; w2.y = w.y + bias;
            w2.z = w.z + bias; w2.w = w.w + bias;
            *reinterpret_cast<float4*>(&g_outT[row + bb]) = w2;
        }
    }
}

// ---------------------------------------------------------------------------
// Kernel D(chunk): transpose outT columns [b0..b0+64) -> out rows [b0..b0+64).
// ---------------------------------------------------------------------------
__global__ __launch_bounds__(256)
void transpose_out_chunk(float* __restrict__ out, int b0) {
    __shared__ float tile[32][65];            // tile[e_loc][b_loc]
    const int e0 = blockIdx.x * 32;
    const int tx = threadIdx.x;
    const int ty = threadIdx.y;

    {
        const int e = e0 + ty;
        const size_t row = (size_t)e * B_ + b0;
#pragma unroll
        for (int k = 0; k < 2; k++) {
            const int bb = 4 * (tx + 8 * k);
            float4 v = __ldcs(reinterpret_cast<const float4*>(&g_outT[row + bb]));
            tile[ty][bb + 0] = v.x;
            tile[ty][bb + 1] = v.y;
            tile[ty][bb + 2] = v.z;
            tile[ty][bb + 3] = v.w;
        }
    }
    __syncthreads();
#pragma unroll
    for (int j = 0; j < 2; j++) {
        const int bl = ty + 32 * j;
        float4 w;
        w.x = tile[tx * 4 + 0][bl];
        w.y = tile[tx * 4 + 1][bl];
        w.z = tile[tx * 4 + 2][bl];
        w.w = tile[tx * 4 + 3][bl];
        __stcs(reinterpret_cast<float4*>(out + (size_t)(b0 + bl) * E_ + e0) + tx, w);
    }
}

// Fast ELU: MUFU.EX2-based.
__device__ __forceinline__ float elu1(float z) {
    return z > 0.0f ? z : __expf(z) - 1.0f;
}

// Vectorized global reduce-add, 16B per lane (sm_90+).
__device__ __forceinline__ void red_add_v4(float* addr, float a, float b,
                                           float c, float d) {
    asm volatile("red.global.add.v4.f32 [%0], {%1, %2, %3, %4};"
                 :: "l"(addr), "f"(a), "f"(b), "f"(c), "f"(d)
                 : "memory");
}

// ---------------------------------------------------------------------------
// Kernel C(chunk): 2 function nodes per 128-thread block; 64 lanes = 64 batch
// columns [b0..b0+64). Same math as the proven fn_node body.
// ---------------------------------------------------------------------------
__global__ __launch_bounds__(128)
void fn_node_chunk(const float* __restrict__ s,
                   const float* __restrict__ w1,
                   const float* __restrict__ b1,
                   const float* __restrict__ w2,
                   const float* __restrict__ b2,
                   const float* __restrict__ w3,
                   const int*   __restrict__ src1,
                   const int*   __restrict__ dst3,
                   const float* __restrict__ g1,
                   const float* __restrict__ bt1,
                   const float* __restrict__ g2,
                   const float* __restrict__ bt2,
                   int b0) {
    __shared__ float w1s[2][DIN_ * C_];
    __shared__ float w2s[2][C_ * C_];
    __shared__ float w3s[2][DOUT_ * C_];
    __shared__ int   ine[2][DIN_];
    __shared__ int   oute[2][DOUT_];
    __shared__ float b1s[2][C_], b2s[2][C_];
    __shared__ float g1s[2][C_], bt1s[2][C_], g2s[2][C_], bt2s[2][C_];
    __shared__ __align__(16) float sc[2][DOUT_][CB_];

    const int tid  = threadIdx.x;
    const int half = tid >> 6;
    const int lane = tid & 63;
    const int f    = blockIdx.x * 2 + half;
    const int b    = b0 + lane;

    // s loads first (streaming; long latency overlaps staging)
    const float4* srow = reinterpret_cast<const float4*>(s + (size_t)b * H_ + f * C_);
    float4 sa = __ldcs(srow);
    float4 sb = __ldcs(srow + 1);

    // param staging (64 threads per f)
#pragma unroll
    for (int k = lane; k < DIN_ * C_; k += 64) w1s[half][k] = w1[f * (DIN_ * C_) + k];
    w2s[half][lane] = w2[f * (C_ * C_) + lane];
#pragma unroll
    for (int k = lane; k < DOUT_ * C_; k += 64) w3s[half][k] = w3[f * (DOUT_ * C_) + k];
    if (lane < DIN_)  ine[half][lane]  = src1[(f * DIN_ + lane) * C_];
    if (lane < DOUT_) oute[half][lane] = dst3[(f * DOUT_ + lane) * C_];
    if (lane < C_) {
        int hc = f * C_ + lane;
        b1s[half][lane]  = b1[hc];
        b2s[half][lane]  = b2[hc];
        g1s[half][lane]  = g1[hc];
        bt1s[half][lane] = bt1[hc];
        g2s[half][lane]  = g2[hc];
        bt2s[half][lane] = bt2[hc];
    }
    __syncthreads();

    // gather (coalesced: 64 consecutive floats per row-half)
    float xv[DIN_];
#pragma unroll
    for (int d = 0; d < DIN_; d++)
        xv[d] = __ldg(&g_xT[(size_t)ine[half][d] * B_ + b]);

    float sv[C_] = {sa.x, sa.y, sa.z, sa.w, sb.x, sb.y, sb.z, sb.w};

    // w1: 10x8 dense
    float h[C_];
#pragma unroll
    for (int c = 0; c < C_; c++) {
        float acc = b1s[half][c];
#pragma unroll
        for (int d = 0; d < DIN_; d++) acc = fmaf(xv[d], w1s[half][d * C_ + c], acc);
        h[c] = acc;
    }

    // groupLN 1 + affine + elu(s*h)
    {
        float sum = 0.f, sq = 0.f;
#pragma unroll
        for (int c = 0; c < C_; c++) { sum += h[c]; sq += h[c] * h[c]; }
        float mu  = sum * 0.125f;
        float var = sq * 0.125f - mu * mu;
        float inv = rsqrtf(var + EPS_);
#pragma unroll
        for (int c = 0; c < C_; c++) {
            float z = (g1s[half][c] * ((h[c] - mu) * inv) + bt1s[half][c]) * sv[c];
            h[c] = elu1(z);
        }
    }

    // w2: 8x8 dense block
    float h2[C_];
#pragma unroll
    for (int c2 = 0; c2 < C_; c2++) {
        float acc = b2s[half][c2];
#pragma unroll
        for (int c = 0; c < C_; c++) acc = fmaf(h[c], w2s[half][c * C_ + c2], acc);
        h2[c2] = acc;
    }

    // groupLN 2 + affine + elu(h*s)
    {
        float sum = 0.f, sq = 0.f;
#pragma unroll
        for (int c = 0; c < C_; c++) { sum += h2[c]; sq += h2[c] * h2[c]; }
        float mu  = sum * 0.125f;
        float var = sq * 0.125f - mu * mu;
        float inv = rsqrtf(var + EPS_);
#pragma unroll
        for (int c = 0; c < C_; c++) {
            float z = (g2s[half][c] * ((h2[c] - mu) * inv) + bt2s[half][c]) * sv[c];
            h[c] = elu1(z);
        }
    }

    // w3 projection staged to smem
#pragma unroll
    for (int d = 0; d < DOUT_; d++) {
        float acc = 0.f;
#pragma unroll
        for (int c = 0; c < C_; c++) acc = fmaf(h[c], w3s[half][d * C_ + c], acc);
        sc[half][d][lane] = acc;
    }
    __syncthreads();

    // scatter: 2 halves x 10 edges x 16 float4 lanes = 320 red.v4 ops
    for (int i = tid; i < 2 * DOUT_ * 16; i += 128) {
        int hh  = i / (DOUT_ * 16);
        int rem = i - hh * (DOUT_ * 16);
        int d   = rem >> 4;
        int l   = rem & 15;
        const float* v = &sc[hh][d][l * 4];
        red_add_v4(&g_outT[(size_t)oute[hh][d] * B_ + b0 + l * 4],
                   v[0], v[1], v[2], v[3]);
    }
}

// ---------------------------------------------------------------------------
// Launch: two independent batch-chunk chains on two streams (event fork/join).
// ---------------------------------------------------------------------------
extern "C" void kernel_launch(void* const* d_in, const int* in_sizes, int n_in,
                              void* d_out, int out_size) {
    const float* x   = (const float*)d_in[0];
    const float* s   = (const float*)d_in[1];
    const float* w1  = (const float*)d_in[2];
    const float* b1  = (const float*)d_in[3];
    const float* w2  = (const float*)d_in[4];
    const float* b2  = (const float*)d_in[5];
    const float* w3  = (const float*)d_in[6];
    const float* b3  = (const float*)d_in[7];
    const float* g1  = (const float*)d_in[8];
    const float* bt1 = (const float*)d_in[9];
    const float* g2  = (const float*)d_in[10];
    const float* bt2 = (const float*)d_in[11];
    const int*   src1 = (const int*)d_in[12];
    const int*   dst3 = (const int*)d_in[17];
    float* out = (float*)d_out;

    // One-time handles (no device memory allocated; graph identical per call).
    static cudaStream_t s2 = nullptr;
    static cudaEvent_t evFork = nullptr, evJoin = nullptr;
    if (s2 == nullptr) {
        cudaStreamCreateWithFlags(&s2, cudaStreamNonBlocking);
        cudaEventCreateWithFlags(&evFork, cudaEventDisableTiming);
        cudaEventCreateWithFlags(&evJoin, cudaEventDisableTiming);
    }

    // Prep: used-edge flags (before fork; both chains read them).
    {
        void* usedPtr = nullptr;
        cudaGetSymbolAddress(&usedPtr, g_used);
        cudaMemsetAsync(usedPtr, 0, E_);
        mark_used_kernel<<<(F_ * DIN_ + 255) / 256, 256>>>(src1);
    }

    cudaEventRecord(evFork, 0);
    cudaStreamWaitEvent(s2, evFork, 0);

    dim3 tblk(8, 32);
    const int tgrid = E_ / 32;   // 3125

    // Chain 0 (columns 0..63) on the capture stream.
    transpose_init_chunk<<<tgrid, tblk>>>(x, b3, 0);
    fn_node_chunk<<<F_ / 2, 128>>>(s, w1, b1, w2, b2, w3,
                                   src1, dst3, g1, bt1, g2, bt2, 0);
    transpose_out_chunk<<<tgrid, tblk>>>(out, 0);

    // Chain 1 (columns 64..127) on s2.
    transpose_init_chunk<<<tgrid, tblk, 0, s2>>>(x, b3, CB_);
    fn_node_chunk<<<F_ / 2, 128, 0, s2>>>(s, w1, b1, w2, b2, w3,
                                          src1, dst3, g1, bt1, g2, bt2, CB_);
    transpose_out_chunk<<<tgrid, tblk, 0, s2>>>(out, CB_);

    cudaEventRecord(evJoin, s2);
    cudaStreamWaitEvent(0, evJoin, 0);
}